// round 1
// baseline (speedup 1.0000x reference)
#include <cuda_runtime.h>
#include <cuda_bf16.h>
#include <math.h>

// ---------------------------------------------------------------------------
// Problem constants: B=2, Cin=Cout=64, H=W=80, branches k in {3,5,7}
// out: (2, 192, 80, 80) fp32
// ---------------------------------------------------------------------------
#define HH 80
#define WW 80
#define HW 6400
#define CIN 64

// ---------------------------------------------------------------------------
// Device scratch (no allocations allowed)
// ---------------------------------------------------------------------------
__device__ float g_om3[2 * 27 * HW];    // offset+mask conv output, branch k=3
__device__ float g_om5[2 * 75 * HW];    // k=5
__device__ float g_om7[2 * 147 * HW];   // k=7

__device__ float g_wcv3[64 * 3 * 27 * 4];    // transposed conv weights [cin][ty][c][txp]
__device__ float g_wcv5[64 * 5 * 75 * 8];
__device__ float g_wcv7[64 * 7 * 147 * 8];

__device__ float g_wd3[9 * 64 * 64];    // transposed dcn weights [t][o][cin]
__device__ float g_wd5[25 * 64 * 64];
__device__ float g_wd7[49 * 64 * 64];

template <int BR> __device__ __forceinline__ float* om_ptr() {
    return BR == 0 ? g_om3 : (BR == 1 ? g_om5 : g_om7);
}
template <int BR> __device__ __forceinline__ float* wcv_ptr() {
    return BR == 0 ? g_wcv3 : (BR == 1 ? g_wcv5 : g_wcv7);
}
template <int BR> __device__ __forceinline__ float* wd_ptr() {
    return BR == 0 ? g_wd3 : (BR == 1 ? g_wd5 : g_wd7);
}

// ---------------------------------------------------------------------------
// Prep: transpose weights into FMA-friendly layouts.
//   conv:  wcv[((cin*K + ty)*NCH + c)*TXP + tx]  (tx zero-padded to TXP)
//   dcn:   wd[(t*64 + o)*64 + cin]
// ---------------------------------------------------------------------------
template <int K, int BR>
__global__ void prep_weights(const float* __restrict__ w_off,
                             const float* __restrict__ w_mask,
                             const float* __restrict__ w_dcn)
{
    constexpr int KK  = K * K;
    constexpr int NCH = 3 * KK;
    constexpr int TXP = (K <= 3) ? 4 : 8;
    const int N1 = 64 * K * NCH * TXP;
    const int N2 = KK * 64 * 64;
    float* wcv = wcv_ptr<BR>();
    float* wd  = wd_ptr<BR>();

    for (int i = blockIdx.x * blockDim.x + threadIdx.x; i < N1 + N2;
         i += gridDim.x * blockDim.x) {
        if (i < N1) {
            int tx  = i % TXP;
            int c   = (i / TXP) % NCH;
            int ty  = (i / (TXP * NCH)) % K;
            int cin = i / (TXP * NCH * K);
            float v = 0.f;
            if (tx < K) {
                if (c < 2 * KK)
                    v = w_off[((c * 64 + cin) * K + ty) * K + tx];
                else
                    v = w_mask[(((c - 2 * KK) * 64 + cin) * K + ty) * K + tx];
            }
            wcv[i] = v;
        } else {
            int j   = i - N1;
            int cin = j & 63;
            int o   = (j >> 6) & 63;
            int t   = j >> 12;
            wd[j] = w_dcn[(o * 64 + cin) * KK + t];
        }
    }
}

// ---------------------------------------------------------------------------
// Conv kernel: computes the fused offset(2kk)+mask(kk) conv for one branch.
// Tile: TH=2 rows x TW=16 cols = 32 output pixels per CTA.
// Threads = G*8:  quad = tid&7 (8 pixel-quads), cgroup = tid>>3 (G groups).
// Each thread owns CPT channels x 4 pixels.
// ---------------------------------------------------------------------------
template <int K, int BR>
__global__ void conv_off_mask(const float* __restrict__ x,
                              const float* __restrict__ b_off,
                              const float* __restrict__ b_mask)
{
    constexpr int KK   = K * K;
    constexpr int NCH  = 3 * KK;                         // 27 / 75 / 147
    constexpr int G    = (K == 3) ? 27 : (K == 5 ? 25 : 21);
    constexpr int CPT  = NCH / G;                        // 1 / 3 / 7
    constexpr int TXP  = (K <= 3) ? 4 : 8;
    constexpr int PAD  = K / 2;
    constexpr int ROWS = K + 1;                          // TH + K - 1
    constexpr int TWH  = 16 + K - 1;                     // halo width
    constexpr int TWP  = (K == 7) ? 24 : 20;             // padded halo width (mult of 4)
    constexpr int WREG = (K == 7) ? 12 : 8;

    extern __shared__ __align__(16) float xs[];          // [ROWS][64][TWP]

    const int tid = threadIdx.x;
    const int nth = blockDim.x;
    const int b   = blockIdx.z;
    const int h0  = blockIdx.y * 2;
    const int w0  = blockIdx.x * 16;

    // --- load halo tile into smem ---
    const float* xb = x + (size_t)b * CIN * HW;
    const int hb = h0 - PAD, wb = w0 - PAD;
    for (int i = tid; i < ROWS * 64 * TWH; i += nth) {
        int col  = i % TWH;
        int rest = i / TWH;
        int cin  = rest % 64;
        int row  = rest / 64;
        int gh = hb + row, gw = wb + col;
        float v = 0.f;
        if (gh >= 0 && gh < HH && gw >= 0 && gw < WW)
            v = xb[(cin * HH + gh) * WW + gw];
        xs[(row * 64 + cin) * TWP + col] = v;
    }
    __syncthreads();

    const int quad = tid & 7;
    const int cg   = tid >> 3;
    const int qrow = quad >> 2;
    const int wq   = (quad & 3) * 4;

    float acc[CPT][4];
#pragma unroll
    for (int j = 0; j < CPT; j++)
#pragma unroll
        for (int p = 0; p < 4; p++) acc[j][p] = 0.f;

    const float* wcv = wcv_ptr<BR>();

    for (int cin = 0; cin < 64; cin++) {
        for (int ty = 0; ty < K; ty++) {
            const float* xrow = &xs[((qrow + ty) * 64 + cin) * TWP + wq];
            float xw[WREG];
#pragma unroll
            for (int q = 0; q < WREG / 4; q++)
                *(float4*)(xw + 4 * q) = *(const float4*)(xrow + 4 * q);

            const float* wrow = wcv + (size_t)(cin * K + ty) * NCH * TXP;
#pragma unroll
            for (int j = 0; j < CPT; j++) {
                const int c = cg + j * G;
                float wt[TXP];
#pragma unroll
                for (int q = 0; q < TXP / 4; q++)
                    *(float4*)(wt + 4 * q) = *(const float4*)(wrow + c * TXP + 4 * q);
#pragma unroll
                for (int tx = 0; tx < K; tx++)
#pragma unroll
                    for (int p = 0; p < 4; p++)
                        acc[j][p] += wt[tx] * xw[tx + p];
            }
        }
    }

    // --- epilogue: bias, sigmoid for mask channels, write scratch ---
    const int h = h0 + qrow;
    const int w = w0 + wq;
    float* ob = om_ptr<BR>() + (size_t)b * NCH * HW;
#pragma unroll
    for (int j = 0; j < CPT; j++) {
        const int c = cg + j * G;
        float bias = (c < 2 * KK) ? b_off[c] : b_mask[c - 2 * KK];
        float4 v4;
        float v0 = acc[j][0] + bias;
        float v1 = acc[j][1] + bias;
        float v2 = acc[j][2] + bias;
        float v3 = acc[j][3] + bias;
        if (c >= 2 * KK) {
            v0 = 1.f / (1.f + __expf(-v0));
            v1 = 1.f / (1.f + __expf(-v1));
            v2 = 1.f / (1.f + __expf(-v2));
            v3 = 1.f / (1.f + __expf(-v3));
        }
        v4.x = v0; v4.y = v1; v4.z = v2; v4.w = v3;
        *(float4*)&ob[(c * HH + h) * WW + w] = v4;
    }
}

// ---------------------------------------------------------------------------
// Deform kernel: bilinear sampling + per-tap 64x64x16 GEMM accumulation.
// CTA: 128 threads, 16 pixels (one row, w0..w0+15), one batch.
// Phase A (once): compute folded bilinear weights + clamped offsets for all taps.
// Per tap: fill s[64][16] sample tile; accumulate out[64][16] += W_t * s.
// ---------------------------------------------------------------------------
template <int K, int BR>
__global__ void deform_gemm(const float* __restrict__ x,
                            float* __restrict__ out)
{
    constexpr int KK    = K * K;
    constexpr int NCH   = 3 * KK;
    constexpr int PAD   = K / 2;
    constexpr int CBASE = BR * 64;

    __shared__ __align__(16) float s[64][16];
    __shared__ __align__(16) float cw[KK * 16 * 4];
    __shared__ __align__(16) int   ci[KK * 16 * 4];

    const int tid = threadIdx.x;
    const int b   = blockIdx.z;
    const int h   = blockIdx.y;
    const int w0  = blockIdx.x * 16;

    // --- phase A: precompute bilinear weights/offsets for all taps ---
    {
        const float* om = om_ptr<BR>() + (size_t)b * NCH * HW;
        for (int i = tid; i < KK * 16; i += 128) {
            int px = i & 15;
            int t  = i >> 4;
            int w  = w0 + px;
            int pix = h * WW + w;
            float oy = om[(2 * t) * HW + pix];
            float ox = om[(2 * t + 1) * HW + pix];
            float m  = om[(2 * KK + t) * HW + pix];
            float py  = (float)(h - PAD + t / K) + oy;
            float pxf = (float)(w - PAD + t % K) + ox;
            float y0f = floorf(py);
            float x0f = floorf(pxf);
            float ly = py - y0f, lx = pxf - x0f;
            bool vy0 = (y0f >= 0.f) && (y0f <= 79.f);
            bool vy1 = (y0f >= -1.f) && (y0f <= 78.f);
            bool vx0 = (x0f >= 0.f) && (x0f <= 79.f);
            bool vx1 = (x0f >= -1.f) && (x0f <= 78.f);
            int iy0 = (int)fmaxf(fminf(y0f, 80.f), -1.f);
            int ix0 = (int)fmaxf(fminf(x0f, 80.f), -1.f);
            int y0c = max(0, min(79, iy0));
            int y1c = max(0, min(79, iy0 + 1));
            int x0c = max(0, min(79, ix0));
            int x1c = max(0, min(79, ix0 + 1));
            float wy0 = (1.f - ly) * m, wy1 = ly * m;
            float wx0 = 1.f - lx, wx1 = lx;
            float4 a;
            a.x = (vy0 && vx0) ? wy0 * wx0 : 0.f;
            a.y = (vy0 && vx1) ? wy0 * wx1 : 0.f;
            a.z = (vy1 && vx0) ? wy1 * wx0 : 0.f;
            a.w = (vy1 && vx1) ? wy1 * wx1 : 0.f;
            int4 o4;
            o4.x = y0c * WW + x0c;
            o4.y = y0c * WW + x1c;
            o4.z = y1c * WW + x0c;
            o4.w = y1c * WW + x1c;
            *(float4*)&cw[i * 4] = a;
            *(int4*)&ci[i * 4]   = o4;
        }
    }
    __syncthreads();

    const int op = tid & 31;    // output channels op and op+32
    const int pq = tid >> 5;    // pixel quad base pq*4
    float acc0[4] = {0.f, 0.f, 0.f, 0.f};
    float acc1[4] = {0.f, 0.f, 0.f, 0.f};

    const float* wd = wd_ptr<BR>();
    const float* xb = x + (size_t)b * CIN * HW;

    for (int t = 0; t < KK; t++) {
        // --- phase B: bilinear gather into s[64][16] ---
        for (int i2 = tid; i2 < 64 * 16; i2 += 128) {
            int px  = i2 & 15;
            int cin = i2 >> 4;
            float4 a = *(const float4*)&cw[(t * 16 + px) * 4];
            int4  o4 = *(const int4*)&ci[(t * 16 + px) * 4];
            const float* xc = xb + cin * HW;
            s[cin][px] = a.x * xc[o4.x] + a.y * xc[o4.y] +
                         a.z * xc[o4.z] + a.w * xc[o4.w];
        }
        __syncthreads();

        // --- phase C: out[64][16] += W_t[64][64] * s[64][16] ---
        const float* wt = wd + t * 4096;
#pragma unroll 4
        for (int c4 = 0; c4 < 16; c4++) {
            float wav[4], wbv[4];
            *(float4*)wav = *(const float4*)(wt + op * 64 + c4 * 4);
            *(float4*)wbv = *(const float4*)(wt + (op + 32) * 64 + c4 * 4);
#pragma unroll
            for (int j = 0; j < 4; j++) {
                float4 sj = *(const float4*)&s[c4 * 4 + j][pq * 4];
                acc0[0] += wav[j] * sj.x;
                acc0[1] += wav[j] * sj.y;
                acc0[2] += wav[j] * sj.z;
                acc0[3] += wav[j] * sj.w;
                acc1[0] += wbv[j] * sj.x;
                acc1[1] += wbv[j] * sj.y;
                acc1[2] += wbv[j] * sj.z;
                acc1[3] += wbv[j] * sj.w;
            }
        }
        __syncthreads();
    }

    // --- write output ---
    float* ob = out + ((size_t)b * 192 + CBASE + op) * HW + h * WW + w0 + pq * 4;
    *(float4*)ob = make_float4(acc0[0], acc0[1], acc0[2], acc0[3]);
    *(float4*)(ob + 32 * HW) = make_float4(acc1[0], acc1[1], acc1[2], acc1[3]);
}

// ---------------------------------------------------------------------------
// Launch
// ---------------------------------------------------------------------------
extern "C" void kernel_launch(void* const* d_in, const int* in_sizes, int n_in,
                              void* d_out, int out_size)
{
    (void)in_sizes; (void)n_in; (void)out_size;

    const float* x       = (const float*)d_in[0];
    const float* w_off3  = (const float*)d_in[1];
    const float* b_off3  = (const float*)d_in[2];
    const float* w_mask3 = (const float*)d_in[3];
    const float* b_mask3 = (const float*)d_in[4];
    const float* w_dcn3  = (const float*)d_in[5];
    const float* w_off5  = (const float*)d_in[6];
    const float* b_off5  = (const float*)d_in[7];
    const float* w_mask5 = (const float*)d_in[8];
    const float* b_mask5 = (const float*)d_in[9];
    const float* w_dcn5  = (const float*)d_in[10];
    const float* w_off7  = (const float*)d_in[11];
    const float* b_off7  = (const float*)d_in[12];
    const float* w_mask7 = (const float*)d_in[13];
    const float* b_mask7 = (const float*)d_in[14];
    const float* w_dcn7  = (const float*)d_in[15];
    float* out = (float*)d_out;

    // weight transposes (cheap, rerun every launch; deterministic)
    {
        const int n3 = 64 * 3 * 27 * 4 + 9 * 4096;
        const int n5 = 64 * 5 * 75 * 8 + 25 * 4096;
        const int n7 = 64 * 7 * 147 * 8 + 49 * 4096;
        prep_weights<3, 0><<<(n3 + 255) / 256, 256>>>(w_off3, w_mask3, w_dcn3);
        prep_weights<5, 1><<<(n5 + 255) / 256, 256>>>(w_off5, w_mask5, w_dcn5);
        prep_weights<7, 2><<<(n7 + 255) / 256, 256>>>(w_off7, w_mask7, w_dcn7);
    }

    // offset + mask convolutions
    const int smem3 = 4 * 64 * 20 * 4;   // 20.5 KB
    const int smem5 = 6 * 64 * 20 * 4;   // 30.7 KB
    const int smem7 = 8 * 64 * 24 * 4;   // 49.2 KB
    cudaFuncSetAttribute(conv_off_mask<7, 2>,
                         cudaFuncAttributeMaxDynamicSharedMemorySize, smem7);
    conv_off_mask<3, 0><<<dim3(5, 40, 2), 27 * 8, smem3>>>(x, b_off3, b_mask3);
    conv_off_mask<5, 1><<<dim3(5, 40, 2), 25 * 8, smem5>>>(x, b_off5, b_mask5);
    conv_off_mask<7, 2><<<dim3(5, 40, 2), 21 * 8, smem7>>>(x, b_off7, b_mask7);

    // deformable sampling + DCN einsum
    deform_gemm<3, 0><<<dim3(5, 80, 2), 128>>>(x, out);
    deform_gemm<5, 1><<<dim3(5, 80, 2), 128>>>(x, out);
    deform_gemm<7, 2><<<dim3(5, 80, 2), 128>>>(x, out);
}

// round 2
// speedup vs baseline: 1.8181x; 1.8181x over previous
#include <cuda_runtime.h>
#include <cuda_bf16.h>
#include <math.h>

// ---------------------------------------------------------------------------
// Problem constants: B=2, Cin=Cout=64, H=W=80, branches k in {3,5,7}
// ---------------------------------------------------------------------------
#define HH 80
#define WW 80
#define HW 6400
#define CIN 64

typedef unsigned long long u64;

__device__ __forceinline__ void ffma2(u64& d, u64 a, u64 b) {
    asm("fma.rn.f32x2 %0, %1, %2, %0;" : "+l"(d) : "l"(a), "l"(b));
}
__device__ __forceinline__ float2 unpk(u64 v) {
    float2 r;
    asm("mov.b64 {%0, %1}, %2;" : "=f"(r.x), "=f"(r.y) : "l"(v));
    return r;
}

// ---------------------------------------------------------------------------
// Device scratch
// ---------------------------------------------------------------------------
__device__ float g_om3[2 * 27 * HW];
__device__ float g_om5[2 * 75 * HW];
__device__ float g_om7[2 * 147 * HW];

// conv weights: packed channel pairs, [((cin*K+ty)*K+tx)*NPAIR + cp] = (w[2cp], w[2cp+1])
__device__ __align__(16) float2 g_wcv3[64 * 9 * 14];
__device__ __align__(16) float2 g_wcv5[64 * 25 * 38];
__device__ __align__(16) float2 g_wcv7[64 * 49 * 74];

// dcn weights: duplicated pairs, [(t*64+cin)*64 + och] = (w, w)
__device__ __align__(16) float2 g_wd3[9 * 64 * 64];
__device__ __align__(16) float2 g_wd5[25 * 64 * 64];
__device__ __align__(16) float2 g_wd7[49 * 64 * 64];

template <int BR> __device__ __forceinline__ float* om_ptr() {
    return BR == 0 ? g_om3 : (BR == 1 ? g_om5 : g_om7);
}
template <int BR> __device__ __forceinline__ float2* wcv_ptr() {
    return BR == 0 ? g_wcv3 : (BR == 1 ? g_wcv5 : g_wcv7);
}
template <int BR> __device__ __forceinline__ float2* wd_ptr() {
    return BR == 0 ? g_wd3 : (BR == 1 ? g_wd5 : g_wd7);
}

// ---------------------------------------------------------------------------
// Prep: transpose weights into the packed layouts above.
// ---------------------------------------------------------------------------
template <int K, int BR>
__global__ void prep_weights(const float* __restrict__ w_off,
                             const float* __restrict__ w_mask,
                             const float* __restrict__ w_dcn)
{
    constexpr int KK    = K * K;
    constexpr int NCH   = 3 * KK;
    constexpr int NPAIR = (NCH + 1) / 2;
    const int N1 = 64 * K * K * NPAIR;     // float2 elements (conv)
    const int N2 = KK * 64 * 64;           // float2 elements (dcn dup)
    float2* wcv = wcv_ptr<BR>();
    float2* wd  = wd_ptr<BR>();

    for (int i = blockIdx.x * blockDim.x + threadIdx.x; i < N1 + N2;
         i += gridDim.x * blockDim.x) {
        if (i < N1) {
            int cp   = i % NPAIR;
            int rest = i / NPAIR;
            int tx   = rest % K;
            int ty   = (rest / K) % K;
            int cin  = rest / (K * K);
            float va = 0.f, vb = 0.f;
            int c1 = 2 * cp, c2 = 2 * cp + 1;
            if (c1 < 2 * KK)      va = w_off[((c1 * 64 + cin) * K + ty) * K + tx];
            else                  va = w_mask[(((c1 - 2 * KK) * 64 + cin) * K + ty) * K + tx];
            if (c2 < NCH) {
                if (c2 < 2 * KK)  vb = w_off[((c2 * 64 + cin) * K + ty) * K + tx];
                else              vb = w_mask[(((c2 - 2 * KK) * 64 + cin) * K + ty) * K + tx];
            }
            wcv[i] = make_float2(va, vb);
        } else {
            int j   = i - N1;
            int och = j & 63;
            int cin = (j >> 6) & 63;
            int t   = j >> 12;
            float v = w_dcn[(och * 64 + cin) * KK + t];
            wd[j] = make_float2(v, v);
        }
    }
}

// ---------------------------------------------------------------------------
// Conv kernel (offset + mask). Thread = 1 channel-pair x 16 pixels (one row).
// x tile lives in smem as DUPLICATED float2 (v,v) -> FFMA2 b-operand is a
// plain LDS. Weights via coalesced LDG.64 (lanes = consecutive cp).
// ---------------------------------------------------------------------------
template <int K, int BR>
__global__ void __launch_bounds__((K == 3) ? 64 : 160)
conv_off_mask(const float* __restrict__ x,
              const float* __restrict__ b_off,
              const float* __restrict__ b_mask)
{
    constexpr int KK    = K * K;
    constexpr int NCH   = 3 * KK;
    constexpr int NPAIR = (NCH + 1) / 2;               // 14 / 38 / 74
    constexpr int TR    = (K == 7) ? 2 : 4;            // rows per CTA
    constexpr int CGD   = (K == 3) ? 16 : (K == 5 ? 40 : 80);
    constexpr int PAD   = K / 2;
    constexpr int ROWS  = TR + K - 1;
    constexpr int TWH   = 16 + K - 1;                  // 18 / 20 / 22 (even)

    extern __shared__ __align__(16) float2 xs[];       // [ROWS][64][TWH] duplicated

    const int tid = threadIdx.x;
    const int nth = blockDim.x;
    const int b   = blockIdx.z;
    const int h0  = blockIdx.y * TR;
    const int w0  = blockIdx.x * 16;

    // halo fill (duplicated)
    const float* xb = x + (size_t)b * CIN * HW;
    const int hb = h0 - PAD, wb = w0 - PAD;
    for (int i = tid; i < ROWS * 64 * TWH; i += nth) {
        int col  = i % TWH;
        int rest = i / TWH;
        int cin  = rest & 63;
        int row  = rest >> 6;
        int gh = hb + row, gw = wb + col;
        float v = 0.f;
        if (gh >= 0 && gh < HH && gw >= 0 && gw < WW)
            v = xb[(cin * HH + gh) * WW + gw];
        xs[i] = make_float2(v, v);
    }
    __syncthreads();

    const int cg = tid % CGD;
    const int r  = tid / CGD;
    const int cp = (cg < NPAIR) ? cg : (NPAIR - 1);

    u64 acc2[16];
#pragma unroll
    for (int p = 0; p < 16; p++) acc2[p] = 0ull;

    const float2* wcv = wcv_ptr<BR>();

    for (int cin = 0; cin < 64; cin++) {
#pragma unroll
        for (int ty = 0; ty < K; ty++) {
            const ulonglong2* xrow =
                (const ulonglong2*)&xs[((r + ty) * 64 + cin) * TWH];
            u64 xw[TWH];
#pragma unroll
            for (int q = 0; q < TWH / 2; q++) {
                ulonglong2 t2 = xrow[q];
                xw[2 * q]     = t2.x;
                xw[2 * q + 1] = t2.y;
            }
            const float2* wrow = wcv + (size_t)((cin * K + ty) * K) * NPAIR + cp;
            u64 wt[K];
#pragma unroll
            for (int tx = 0; tx < K; tx++)
                wt[tx] = *(const u64*)(wrow + tx * NPAIR);
#pragma unroll
            for (int tx = 0; tx < K; tx++)
#pragma unroll
                for (int p = 0; p < 16; p++)
                    ffma2(acc2[p], wt[tx], xw[tx + p]);
        }
    }

    if (cg < NPAIR) {
        const int c1 = 2 * cp;
        const bool two    = (c1 + 1 < NCH);
        const bool ismask = (c1 >= 2 * KK);   // pairs never straddle (2KK even)
        float blo = ismask ? b_mask[c1 - 2 * KK] : b_off[c1];
        float bhi = 0.f;
        if (two) bhi = ismask ? b_mask[c1 + 1 - 2 * KK] : b_off[c1 + 1];

        float lo[16], hi[16];
#pragma unroll
        for (int p = 0; p < 16; p++) {
            float2 v = unpk(acc2[p]);
            lo[p] = v.x + blo;
            hi[p] = v.y + bhi;
        }
        if (ismask) {
#pragma unroll
            for (int p = 0; p < 16; p++) {
                lo[p] = 1.f / (1.f + __expf(-lo[p]));
                hi[p] = 1.f / (1.f + __expf(-hi[p]));
            }
        }
        const int h = h0 + r;
        float* ob = om_ptr<BR>() + (size_t)b * NCH * HW;
        float* p1 = &ob[(c1 * HH + h) * WW + w0];
#pragma unroll
        for (int q = 0; q < 4; q++)
            *(float4*)(p1 + 4 * q) =
                make_float4(lo[4 * q], lo[4 * q + 1], lo[4 * q + 2], lo[4 * q + 3]);
        if (two) {
            float* p2 = p1 + HW;
#pragma unroll
            for (int q = 0; q < 4; q++)
                *(float4*)(p2 + 4 * q) =
                    make_float4(hi[4 * q], hi[4 * q + 1], hi[4 * q + 2], hi[4 * q + 3]);
        }
    }
}

// ---------------------------------------------------------------------------
// Deform kernel. CTA = 128 threads, 2x16 pixel tile, one batch.
// Per tap: phase A (32 threads: bilinear coeffs), gather s[64][32] (lanes =
// consecutive px for coalescing), FFMA2 GEMM out[64][32] += dup(W_t) * s.
// Thread tile = 4 och x 4 px (2 pixel pairs).
// ---------------------------------------------------------------------------
template <int K, int BR>
__global__ void __launch_bounds__(128)
deform_gemm(const float* __restrict__ x, float* __restrict__ out)
{
    constexpr int KK    = K * K;
    constexpr int NCH   = 3 * KK;
    constexpr int PAD   = K / 2;
    constexpr int CBASE = BR * 64;

    __shared__ __align__(16) float s[64][32];
    __shared__ __align__(16) float4 cwT[32];
    __shared__ __align__(16) int4   ciT[32];

    const int tid = threadIdx.x;
    const int b   = blockIdx.z;
    const int h0  = blockIdx.y * 2;
    const int w0  = blockIdx.x * 16;

    const int og = tid >> 3;   // 16 groups of 4 output channels
    const int pq = tid & 7;    // 8 quads of 4 pixels

    u64 acc2[4][2] = {};

    const float2* wd = wd_ptr<BR>();
    const float*  xb = x + (size_t)b * CIN * HW;
    const float*  om = om_ptr<BR>() + (size_t)b * NCH * HW;

    for (int t = 0; t < KK; t++) {
        // --- phase A: bilinear coeffs for the 32 pixels of this tap ---
        if (tid < 32) {
            int px = tid, row = px >> 4, col = px & 15;
            int h = h0 + row, w = w0 + col;
            int pix = h * WW + w;
            float oy = om[(2 * t) * HW + pix];
            float ox = om[(2 * t + 1) * HW + pix];
            float m  = om[(2 * KK + t) * HW + pix];
            float py  = (float)(h - PAD + t / K) + oy;
            float pxf = (float)(w - PAD + t % K) + ox;
            float y0f = floorf(py);
            float x0f = floorf(pxf);
            float ly = py - y0f, lx = pxf - x0f;
            bool vy0 = (y0f >= 0.f) && (y0f <= 79.f);
            bool vy1 = (y0f >= -1.f) && (y0f <= 78.f);
            bool vx0 = (x0f >= 0.f) && (x0f <= 79.f);
            bool vx1 = (x0f >= -1.f) && (x0f <= 78.f);
            int iy0 = (int)fmaxf(fminf(y0f, 80.f), -1.f);
            int ix0 = (int)fmaxf(fminf(x0f, 80.f), -1.f);
            int y0c = max(0, min(79, iy0));
            int y1c = max(0, min(79, iy0 + 1));
            int x0c = max(0, min(79, ix0));
            int x1c = max(0, min(79, ix0 + 1));
            float wy0 = (1.f - ly) * m, wy1 = ly * m;
            float wx0 = 1.f - lx, wx1 = lx;
            float4 a;
            a.x = (vy0 && vx0) ? wy0 * wx0 : 0.f;
            a.y = (vy0 && vx1) ? wy0 * wx1 : 0.f;
            a.z = (vy1 && vx0) ? wy1 * wx0 : 0.f;
            a.w = (vy1 && vx1) ? wy1 * wx1 : 0.f;
            int4 o4;
            o4.x = y0c * WW + x0c;
            o4.y = y0c * WW + x1c;
            o4.z = y1c * WW + x0c;
            o4.w = y1c * WW + x1c;
            cwT[px] = a;
            ciT[px] = o4;
        }
        __syncthreads();

        // --- gather: s[64][32]; lanes cover consecutive px (coalesced) ---
#pragma unroll 4
        for (int j = 0; j < 16; j++) {
            int idx = tid + j * 128;
            int px  = idx & 31;
            int cin = idx >> 5;
            float4 a = cwT[px];
            int4  o4 = ciT[px];
            const float* xc = xb + cin * HW;
            s[cin][px] = a.x * xc[o4.x] + a.y * xc[o4.y] +
                         a.z * xc[o4.z] + a.w * xc[o4.w];
        }
        __syncthreads();

        // --- GEMM: acc[4 och][2 px-pairs] += dup(w) * s-pairs ---
        const float2* wt = wd + (size_t)t * 4096;
#pragma unroll 2
        for (int c4 = 0; c4 < 16; c4++) {
#pragma unroll
            for (int cc = 0; cc < 4; cc++) {
                int cin = c4 * 4 + cc;
                ulonglong2 sv = *(const ulonglong2*)&s[cin][pq * 4];
                const ulonglong2* wr =
                    (const ulonglong2*)(wt + cin * 64 + og * 4);
                ulonglong2 w01 = wr[0];
                ulonglong2 w23 = wr[1];
                ffma2(acc2[0][0], w01.x, sv.x); ffma2(acc2[0][1], w01.x, sv.y);
                ffma2(acc2[1][0], w01.y, sv.x); ffma2(acc2[1][1], w01.y, sv.y);
                ffma2(acc2[2][0], w23.x, sv.x); ffma2(acc2[2][1], w23.x, sv.y);
                ffma2(acc2[3][0], w23.y, sv.x); ffma2(acc2[3][1], w23.y, sv.y);
            }
        }
        __syncthreads();
    }

    // --- write output: 4 och x 4 px per thread ---
    const int row  = pq >> 2;
    const int colb = (pq & 3) * 4;
    float* ob = out + ((size_t)(b * 192 + CBASE + og * 4)) * HW +
                (h0 + row) * WW + w0 + colb;
#pragma unroll
    for (int o = 0; o < 4; o++) {
        float2 v0 = unpk(acc2[o][0]);
        float2 v1 = unpk(acc2[o][1]);
        *(float4*)(ob + (size_t)o * HW) = make_float4(v0.x, v0.y, v1.x, v1.y);
    }
}

// ---------------------------------------------------------------------------
// Launch
// ---------------------------------------------------------------------------
extern "C" void kernel_launch(void* const* d_in, const int* in_sizes, int n_in,
                              void* d_out, int out_size)
{
    (void)in_sizes; (void)n_in; (void)out_size;

    const float* x       = (const float*)d_in[0];
    const float* w_off3  = (const float*)d_in[1];
    const float* b_off3  = (const float*)d_in[2];
    const float* w_mask3 = (const float*)d_in[3];
    const float* b_mask3 = (const float*)d_in[4];
    const float* w_dcn3  = (const float*)d_in[5];
    const float* w_off5  = (const float*)d_in[6];
    const float* b_off5  = (const float*)d_in[7];
    const float* w_mask5 = (const float*)d_in[8];
    const float* b_mask5 = (const float*)d_in[9];
    const float* w_dcn5  = (const float*)d_in[10];
    const float* w_off7  = (const float*)d_in[11];
    const float* b_off7  = (const float*)d_in[12];
    const float* w_mask7 = (const float*)d_in[13];
    const float* b_mask7 = (const float*)d_in[14];
    const float* w_dcn7  = (const float*)d_in[15];
    float* out = (float*)d_out;

    // weight repacking
    {
        const int n3 = 64 * 9 * 14 + 9 * 4096;       // 44928
        const int n5 = 64 * 25 * 38 + 25 * 4096;     // 163200
        const int n7 = 64 * 49 * 74 + 49 * 4096;     // 432768
        prep_weights<3, 0><<<(n3 + 255) / 256, 256>>>(w_off3, w_mask3, w_dcn3);
        prep_weights<5, 1><<<(n5 + 255) / 256, 256>>>(w_off5, w_mask5, w_dcn5);
        prep_weights<7, 2><<<(n7 + 255) / 256, 256>>>(w_off7, w_mask7, w_dcn7);
    }

    // offset + mask convs (dup-float2 smem tiles)
    const int smem3 = 6 * 64 * 18 * 8;   // 55.3 KB
    const int smem5 = 8 * 64 * 20 * 8;   // 81.9 KB
    const int smem7 = 8 * 64 * 22 * 8;   // 90.1 KB
    cudaFuncSetAttribute(conv_off_mask<3, 0>,
                         cudaFuncAttributeMaxDynamicSharedMemorySize, smem3);
    cudaFuncSetAttribute(conv_off_mask<5, 1>,
                         cudaFuncAttributeMaxDynamicSharedMemorySize, smem5);
    cudaFuncSetAttribute(conv_off_mask<7, 2>,
                         cudaFuncAttributeMaxDynamicSharedMemorySize, smem7);
    conv_off_mask<3, 0><<<dim3(5, 20, 2), 64,  smem3>>>(x, b_off3, b_mask3);
    conv_off_mask<5, 1><<<dim3(5, 20, 2), 160, smem5>>>(x, b_off5, b_mask5);
    conv_off_mask<7, 2><<<dim3(5, 40, 2), 160, smem7>>>(x, b_off7, b_mask7);

    // deformable sampling + DCN einsum
    deform_gemm<3, 0><<<dim3(5, 40, 2), 128>>>(x, out);
    deform_gemm<5, 1><<<dim3(5, 40, 2), 128>>>(x, out);
    deform_gemm<7, 2><<<dim3(5, 40, 2), 128>>>(x, out);
}